// round 13
// baseline (speedup 1.0000x reference)
#include <cuda_runtime.h>
#include <cuda_fp16.h>
#include <cstdint>

// ============================================================================
// FastTSAGEConv fused kernel for GB300 (plain sm_103 PTX feature set):
// legacy HMMA mma.sync.m16n8k16 fp16 (fp32 accum), 1-pass.
//
//   ss = seg_start (dst_deg = dst_max_eid - seg_start + 1)
//   hn[e]  = (sum_{j=ss..me} src_feat[j]) / (deg[e]+1)
//   out[e] = [dst_feat[e] | hn[e]] @ [W_self; W_neigh] + (b_self + b_neigh)
//
// R12 = R11 resubmission (container failed twice with no compile/bench output;
// loop-termination audit found no unbounded path -> infra flake hypothesis).
// Composition of the two separately-validated levers:
//   (a) OCC 4 (R6: 4th CTA won at 64-reg cap despite spills)
//   (b) dual-chain interleaved producer (R10: +4% at iso-occupancy)
// Register relief: branchless dme low-word read (dme32[e << sh], valid for
// both i32/i64 since values < 2^31, little-endian), pointer-stride walk for
// B-fragment loads (less per-iteration ALU).
// ============================================================================

#define TILE_M     64
#define NTHREADS   256
#define OCC        4

// ---- smem layout: A tile + aliased out-stage ----
static constexpr int A_STRIDE_B = 528;          // bytes per A row (256 fp16 + 8 pad)
static constexpr int STG_STRIDE = 136;          // floats per out-stage row (pad 8)
// A fp16 [64][528B] = 33792 B ; out stage fp32 [64][136] = 34816 B (aliased)
static constexpr int SMEM_TOTAL = TILE_M * STG_STRIDE * 4;   // 34816

// Pre-packed B fragments: [kstep 0..15][nblock 0..15][lane 0..31] x 2 u32
// (64 KB, stays hot in L1 across the whole kernel)
__device__ uint2 g_bfrag[16 * 16 * 32];
// dtype shift for dst_max_eid: 1 if int64 (element word index = e<<1), 0 if int32
__device__ int g_eid_shift;

// ============================ helpers ===================================
__device__ __forceinline__ uint32_t smem_to_u32(const void* smem_ptr) {
    uint32_t addr;
    asm("{ .reg .u64 tmp; cvta.to.shared.u64 tmp, %1; cvt.u32.u64 %0, tmp; }"
        : "=r"(addr) : "l"(smem_ptr));
    return addr;
}

__device__ __forceinline__ uint32_t f22u(float a, float b) {
    __half2 h = __floats2half2_rn(a, b);
    return *reinterpret_cast<uint32_t*>(&h);
}

__device__ __forceinline__ void mma16816(float* c, const uint32_t* a,
                                         uint32_t b0, uint32_t b1) {
    asm volatile(
        "mma.sync.aligned.m16n8k16.row.col.f32.f16.f16.f32 "
        "{%0,%1,%2,%3}, {%4,%5,%6,%7}, {%8,%9}, {%0,%1,%2,%3};\n"
        : "+f"(c[0]), "+f"(c[1]), "+f"(c[2]), "+f"(c[3])
        : "r"(a[0]), "r"(a[1]), "r"(a[2]), "r"(a[3]), "r"(b0), "r"(b1));
}

// ============================================================================
// Prep kernel (also hosts the dtype probe in block 0): pack
// B = [W_self; W_neigh] (256 x 128 f32) into fp16 MMA fragment layout.
// For kstep s (k0=16s), nblock nb (n0=8nb), lane l:
//   kA = 16s + (l%4)*2,  n = 8nb + l/4
//   reg0 = half2( B[kA][n],   B[kA+1][n] )
//   reg1 = half2( B[kA+8][n], B[kA+9][n] )
// Probe: view dst_max_eid as int64 at elements [E/4, E/4+256) (word indices
// < E under either dtype). True int64 (values in [0,E)) => all high words 0;
// int32 data there holds values ~E/2 != 0.
// ============================================================================
__global__ void prep_w_kernel(const float* __restrict__ Wself,
                              const float* __restrict__ Wneigh,
                              const unsigned* __restrict__ dme_words, int E) {
    if (blockIdx.x == 0) {
        __shared__ int nz;
        if (threadIdx.x == 0) nz = 0;
        __syncthreads();
        int i = E / 4 + threadIdx.x;
        unsigned hi = dme_words[2 * i + 1];
        if (hi != 0u) atomicAdd(&nz, 1);
        __syncthreads();
        if (threadIdx.x == 0) g_eid_shift = (nz == 0) ? 1 : 0;
    }
    int idx = blockIdx.x * blockDim.x + threadIdx.x;    // 0..8191
    if (idx >= 16 * 16 * 32) return;
    int lane = idx & 31;
    int nb   = (idx >> 5) & 15;
    int s    = idx >> 9;
    int k0 = s * 16 + (lane & 3) * 2;
    int n  = nb * 8 + (lane >> 2);

    auto wc = [&](int k) -> float {
        return (k < 128) ? Wself[k * 128 + n] : Wneigh[(k - 128) * 128 + n];
    };
    uint2 v;
    v.x = f22u(wc(k0),     wc(k0 + 1));
    v.y = f22u(wc(k0 + 8), wc(k0 + 9));
    g_bfrag[idx] = v;
}

// ============================================================================
// Main persistent kernel — 4 CTAs/SM
// ============================================================================
__global__ void __launch_bounds__(NTHREADS, OCC)
fused_tsage_kernel(const float* __restrict__ src_feat,
                   const float* __restrict__ dst_feat,
                   const int*   __restrict__ dst_max_eid,
                   const float* __restrict__ dst_deg,
                   const float* __restrict__ b_self,
                   const float* __restrict__ b_neigh,
                   float* __restrict__ out,
                   int E, int num_tiles) {
    extern __shared__ char smem[];
    const uint32_t smem_base = smem_to_u32(smem);
    const int tid = threadIdx.x;
    const int wid = tid >> 5;
    const int lid = tid & 31;
    const int wm  = wid & 3;        // M-warp 0..3  (rows wm*16 .. +15)
    const int wn  = wid >> 2;       // N-warp 0..1  (cols wn*64 .. +63)
    // branchless dme access: low word of element e = dst_max_eid[e << sh]
    // (valid for i32 and little-endian i64 with values < 2^31)
    const int sh = g_eid_shift;

    // per-lane bias for the coalesced epilogue (cols 4*lid..4*lid+3)
    const float bia0 = b_self[4 * lid + 0] + b_neigh[4 * lid + 0];
    const float bia1 = b_self[4 * lid + 1] + b_neigh[4 * lid + 1];
    const float bia2 = b_self[4 * lid + 2] + b_neigh[4 * lid + 2];
    const float bia3 = b_self[4 * lid + 3] + b_neigh[4 * lid + 3];

    // ldmatrix per-lane address pieces (A tile, 528B row stride)
    const int ldsm_row = (lid & 7) + ((lid >> 3) & 1) * 8;   // row within 16
    const int ldsm_k16 = (lid >> 4) * 16;                    // +16B for k 8..15
    const uint32_t a_base = smem_base;

    float* stage = reinterpret_cast<float*>(smem);           // fp32 view (aliased)
    // per-warp B fragment pointer (this warp's wn half), L1-resident
    const uint2* __restrict__ bfrag_w = g_bfrag + (size_t)(wn * 8) * 32 + lid;

    const float4 z4 = make_float4(0.f, 0.f, 0.f, 0.f);

    for (int t = blockIdx.x; t < num_tiles; t += gridDim.x) {
        const int m0 = t * TILE_M;

        // ========= producer: 4 pairs of edges, 2 chains interleaved =========
#pragma unroll 1
        for (int u = 0; u < 4; u++) {
            const int r0 = wid * 8 + 2 * u;          // tile row of edge 0
            const int e0 = m0 + r0;                  // edge 0 ; edge 1 = e0+1
            const bool g0 = (e0 < E), g1 = (e0 + 1 < E);

            // dst loads (2 independent, issued first)
            float4 dv0 = z4, dv1 = z4;
            if (g0) dv0 = __ldg(reinterpret_cast<const float4*>(
                dst_feat + (size_t)e0 * 128 + 4 * lid));
            if (g1) dv1 = __ldg(reinterpret_cast<const float4*>(
                dst_feat + (size_t)(e0 + 1) * 128 + 4 * lid));

            // segment metadata (branchless low-word dme reads)
            int me0 = 0, me1 = 0; float dg0 = 0.f, dg1 = 0.f;
            if (g0) { me0 = dst_max_eid[(size_t)e0 << sh];       dg0 = dst_deg[e0]; }
            if (g1) { me1 = dst_max_eid[(size_t)(e0 + 1) << sh]; dg1 = dst_deg[e0 + 1]; }
            if (me0 >= E) me0 = E - 1;  if (me0 < 0) me0 = 0;
            if (me1 >= E) me1 = E - 1;  if (me1 < 0) me1 = 0;
            int ss0 = me0 - (int)dg0 + 1;  if (ss0 < 0) ss0 = 0;
            int ss1 = me1 - (int)dg1 + 1;  if (ss1 < 0) ss1 = 0;
            int c0 = g0 ? (me0 - ss0 + 1) : 0;  if (c0 < 0) c0 = 0;
            int c1 = g1 ? (me1 - ss1 + 1) : 0;  if (c1 < 0) c1 = 0;

            const float4* p0 = reinterpret_cast<const float4*>(
                src_feat + (size_t)ss0 * 128 + 4 * lid);
            const float4* p1 = reinterpret_cast<const float4*>(
                src_feat + (size_t)ss1 * 128 + 4 * lid);

            // interleaved dual-chain segsum: 4 independent loads per iter
            float a0x = 0.f, a0y = 0.f, a0z = 0.f, a0w = 0.f;
            float a1x = 0.f, a1y = 0.f, a1z = 0.f, a1w = 0.f;
            int i0 = 0, i1 = 0;
#pragma unroll 1
            while ((i0 < c0) | (i1 < c1)) {
                float4 x0 = (i0     < c0) ? __ldg(p0 + (size_t)(i0)     * 32) : z4;
                float4 x1 = (i1     < c1) ? __ldg(p1 + (size_t)(i1)     * 32) : z4;
                float4 x2 = (i0 + 1 < c0) ? __ldg(p0 + (size_t)(i0 + 1) * 32) : z4;
                float4 x3 = (i1 + 1 < c1) ? __ldg(p1 + (size_t)(i1 + 1) * 32) : z4;
                a0x += x0.x + x2.x; a0y += x0.y + x2.y;
                a0z += x0.z + x2.z; a0w += x0.w + x2.w;
                a1x += x1.x + x3.x; a1y += x1.y + x3.y;
                a1z += x1.z + x3.z; a1w += x1.w + x3.w;
                i0 += 2; i1 += 2;
            }

            // stores: dst halves + hn halves (fp16)
            if (g0) {
                const float inv0 = 1.0f / (dg0 + 1.0f);
                uint32_t addr = a_base + (uint32_t)r0 * A_STRIDE_B + 8u * lid;
                uint32_t d01 = f22u(dv0.x, dv0.y), d23 = f22u(dv0.z, dv0.w);
                asm volatile("st.shared.v2.b32 [%0], {%1,%2};"
                             :: "r"(addr), "r"(d01), "r"(d23) : "memory");
                uint32_t h01 = f22u(a0x * inv0, a0y * inv0);
                uint32_t h23 = f22u(a0z * inv0, a0w * inv0);
                asm volatile("st.shared.v2.b32 [%0], {%1,%2};"
                             :: "r"(addr + 256u), "r"(h01), "r"(h23) : "memory");
            }
            if (g1) {
                const float inv1 = 1.0f / (dg1 + 1.0f);
                uint32_t addr = a_base + (uint32_t)(r0 + 1) * A_STRIDE_B + 8u * lid;
                uint32_t d01 = f22u(dv1.x, dv1.y), d23 = f22u(dv1.z, dv1.w);
                asm volatile("st.shared.v2.b32 [%0], {%1,%2};"
                             :: "r"(addr), "r"(d01), "r"(d23) : "memory");
                uint32_t h01 = f22u(a1x * inv1, a1y * inv1);
                uint32_t h23 = f22u(a1z * inv1, a1w * inv1);
                asm volatile("st.shared.v2.b32 [%0], {%1,%2};"
                             :: "r"(addr + 256u), "r"(h01), "r"(h23) : "memory");
            }
        }
        __syncthreads();

        // ========= MMA phase: warp tile 16x64, K=256 ========================
        float acc[8][4];
#pragma unroll
        for (int nb = 0; nb < 8; nb++)
#pragma unroll
            for (int q = 0; q < 4; q++) acc[nb][q] = 0.f;

        {
            const uint2* bp = bfrag_w;               // walks +16*32 per s
            uint32_t a_addr = a_base + (uint32_t)(wm * 16 + ldsm_row) * A_STRIDE_B
                            + (uint32_t)ldsm_k16;
#pragma unroll 4
            for (int s = 0; s < 16; s++) {
                uint32_t a[4];
                asm volatile(
                    "ldmatrix.sync.aligned.m8n8.x4.shared.b16 {%0,%1,%2,%3}, [%4];"
                    : "=r"(a[0]), "=r"(a[1]), "=r"(a[2]), "=r"(a[3])
                    : "r"(a_addr));
                a_addr += 32u;
#pragma unroll
                for (int nb = 0; nb < 8; nb++) {
                    uint2 b = __ldg(bp + (size_t)nb * 32);
                    mma16816(acc[nb], a, b.x, b.y);
                }
                bp += 16 * 32;
            }
        }
        __syncthreads();   // all warps done reading A before stage overwrite

        // ========= epilogue: regs -> fp32 stage (aliases A) =================
#pragma unroll
        for (int nb = 0; nb < 8; nb++) {
            const int r0 = wm * 16 + (lid >> 2);
            const int n  = wn * 64 + nb * 8 + (lid & 3) * 2;
            float* p0 = stage + r0 * STG_STRIDE + n;
            p0[0] = acc[nb][0];
            p0[1] = acc[nb][1];
            float* p1 = stage + (r0 + 8) * STG_STRIDE + n;
            p1[0] = acc[nb][2];
            p1[1] = acc[nb][3];
        }
        __syncthreads();

        // ========= coalesced store with bias ================================
#pragma unroll 2
        for (int rr = 0; rr < 8; rr++) {
            const int r = wid * 8 + rr;
            const int e = m0 + r;
            if (e < E) {
                const float* sp = stage + r * STG_STRIDE + 4 * lid;
                float4 v;
                v.x = sp[0] + bia0;
                v.y = sp[1] + bia1;
                v.z = sp[2] + bia2;
                v.w = sp[3] + bia3;
                *reinterpret_cast<float4*>(out + (size_t)e * 128 + 4 * lid) = v;
            }
        }
        __syncthreads();   // stage free before next tile's A writes
    }
}

// ============================================================================
// Launch
// ============================================================================
extern "C" void kernel_launch(void* const* d_in, const int* in_sizes, int n_in,
                              void* d_out, int out_size) {
    const float* src   = (const float*)d_in[0];   // src_feat   [E,128] f32
    const float* dstf  = (const float*)d_in[1];   // dst_feat   [E,128] f32
    // d_in[2] = dst_ids (unused: seg_start = dst_max_eid - deg + 1)
    const int*   dme   = (const int*)  d_in[3];   // dst_max_eid [E] i32 or i64
    const float* deg   = (const float*)d_in[4];   // dst_deg    [E] f32
    const float* Wself = (const float*)d_in[5];   // [128,128] f32
    const float* bself = (const float*)d_in[6];   // [128] f32
    const float* Wnei  = (const float*)d_in[7];   // [128,128] f32
    const float* bnei  = (const float*)d_in[8];   // [128] f32
    float* out = (float*)d_out;

    const int E = in_sizes[4];
    const int num_tiles = (E + TILE_M - 1) / TILE_M;

    prep_w_kernel<<<32, 256>>>(Wself, Wnei, (const unsigned*)dme, E);

    int sm_count = 148;
    cudaDeviceGetAttribute(&sm_count, cudaDevAttrMultiProcessorCount, 0);
    int grid = OCC * sm_count;
    if (grid > num_tiles) grid = num_tiles;

    cudaFuncSetAttribute(fused_tsage_kernel,
                         cudaFuncAttributeMaxDynamicSharedMemorySize, SMEM_TOTAL);
    fused_tsage_kernel<<<grid, NTHREADS, SMEM_TOTAL>>>(
        src, dstf, dme, deg, bself, bnei, out, E, num_tiles);
}

// round 15
// speedup vs baseline: 1.0911x; 1.0911x over previous
#include <cuda_runtime.h>
#include <cuda_fp16.h>
#include <cstdint>

// ============================================================================
// FastTSAGEConv fused kernel for GB300 (plain sm_103 PTX feature set):
// legacy HMMA mma.sync.m16n8k16 fp16 (fp32 accum), 1-pass.
//
//   ss = seg_start (dst_deg = dst_max_eid - seg_start + 1)
//   hn[e]  = (sum_{j=ss..me} src_feat[j]) / (deg[e]+1)
//   out[e] = [dst_feat[e] | hn[e]] @ [W_self; W_neigh] + (b_self + b_neigh)
//
// R13 -> R14: occupancy/ILP axis exhausted (R6 265 / R10 274 / R13 291 all
// bracket the same floor) -> attack the phase structure. The smem out-stage
// existed only for STG coalescing, but DRAM writes are 32B-sector granular
// and direct fragment stores (st.global.v2.f32, 8 rows x 32B per warp-inst)
// touch every sector exactly once. So: store accumulators DIRECTLY, bias from
// a prep-computed g_bias[128] (L1 float2 loads). Removes 2 of 4 barriers/tile
// + ~40 smem ops/warp/tile; smem shrinks to the A tile only.
// Frame = R10 (OCC 3, dual-chain producer, pointer-walk MMA, branchless dme).
// ============================================================================

#define TILE_M     64
#define NTHREADS   256
#define OCC        3

// ---- smem layout: A tile only ----
static constexpr int A_STRIDE_B = 528;          // bytes per A row (256 fp16 + 8 pad)
static constexpr int SMEM_TOTAL = TILE_M * A_STRIDE_B;   // 33792

// Pre-packed B fragments: [kstep 0..15][nblock 0..15][lane 0..31] x 2 u32
// (64 KB, stays hot in L1 across the whole kernel)
__device__ uint2 g_bfrag[16 * 16 * 32];
// combined bias b_self + b_neigh, read as float2 (L1-resident)
__device__ float2 g_bias2[64];
// dtype shift for dst_max_eid: 1 if int64 (low word of e at index e<<1), 0 if int32
__device__ int g_eid_shift;

// ============================ helpers ===================================
__device__ __forceinline__ uint32_t smem_to_u32(const void* smem_ptr) {
    uint32_t addr;
    asm("{ .reg .u64 tmp; cvta.to.shared.u64 tmp, %1; cvt.u32.u64 %0, tmp; }"
        : "=r"(addr) : "l"(smem_ptr));
    return addr;
}

__device__ __forceinline__ uint32_t f22u(float a, float b) {
    __half2 h = __floats2half2_rn(a, b);
    return *reinterpret_cast<uint32_t*>(&h);
}

__device__ __forceinline__ void mma16816(float* c, const uint32_t* a,
                                         uint32_t b0, uint32_t b1) {
    asm volatile(
        "mma.sync.aligned.m16n8k16.row.col.f32.f16.f16.f32 "
        "{%0,%1,%2,%3}, {%4,%5,%6,%7}, {%8,%9}, {%0,%1,%2,%3};\n"
        : "+f"(c[0]), "+f"(c[1]), "+f"(c[2]), "+f"(c[3])
        : "r"(a[0]), "r"(a[1]), "r"(a[2]), "r"(a[3]), "r"(b0), "r"(b1));
}

// ============================================================================
// Prep kernel (dtype probe in block 0, bias pack in block 1): pack
// B = [W_self; W_neigh] (256 x 128 f32) into fp16 MMA fragment layout.
// For kstep s (k0=16s), nblock nb (n0=8nb), lane l:
//   kA = 16s + (l%4)*2,  n = 8nb + l/4
//   reg0 = half2( B[kA][n],   B[kA+1][n] )
//   reg1 = half2( B[kA+8][n], B[kA+9][n] )
// Probe: view dst_max_eid as int64 at elements [E/4, E/4+256) (word indices
// < E under either dtype). True int64 (values in [0,E)) => all high words 0;
// int32 data there holds values ~E/2 != 0.
// ============================================================================
__global__ void prep_w_kernel(const float* __restrict__ Wself,
                              const float* __restrict__ Wneigh,
                              const float* __restrict__ bself,
                              const float* __restrict__ bneigh,
                              const unsigned* __restrict__ dme_words, int E) {
    if (blockIdx.x == 0) {
        __shared__ int nz;
        if (threadIdx.x == 0) nz = 0;
        __syncthreads();
        int i = E / 4 + threadIdx.x;
        unsigned hi = dme_words[2 * i + 1];
        if (hi != 0u) atomicAdd(&nz, 1);
        __syncthreads();
        if (threadIdx.x == 0) g_eid_shift = (nz == 0) ? 1 : 0;
    }
    if (blockIdx.x == 1 && threadIdx.x < 64) {
        int n = threadIdx.x * 2;
        g_bias2[threadIdx.x] = make_float2(bself[n] + bneigh[n],
                                           bself[n + 1] + bneigh[n + 1]);
    }
    int idx = blockIdx.x * blockDim.x + threadIdx.x;    // 0..8191
    if (idx >= 16 * 16 * 32) return;
    int lane = idx & 31;
    int nb   = (idx >> 5) & 15;
    int s    = idx >> 9;
    int k0 = s * 16 + (lane & 3) * 2;
    int n  = nb * 8 + (lane >> 2);

    auto wc = [&](int k) -> float {
        return (k < 128) ? Wself[k * 128 + n] : Wneigh[(k - 128) * 128 + n];
    };
    uint2 v;
    v.x = f22u(wc(k0),     wc(k0 + 1));
    v.y = f22u(wc(k0 + 8), wc(k0 + 9));
    g_bfrag[idx] = v;
}

// ============================================================================
// Main persistent kernel — 3 CTAs/SM
// ============================================================================
__global__ void __launch_bounds__(NTHREADS, OCC)
fused_tsage_kernel(const float* __restrict__ src_feat,
                   const float* __restrict__ dst_feat,
                   const int*   __restrict__ dst_max_eid,
                   const float* __restrict__ dst_deg,
                   float* __restrict__ out,
                   int E, int num_tiles) {
    extern __shared__ char smem[];
    const uint32_t smem_base = smem_to_u32(smem);
    const int tid = threadIdx.x;
    const int wid = tid >> 5;
    const int lid = tid & 31;
    const int wm  = wid & 3;        // M-warp 0..3  (rows wm*16 .. +15)
    const int wn  = wid >> 2;       // N-warp 0..1  (cols wn*64 .. +63)
    // branchless dme access: low word of element e = dst_max_eid[e << sh]
    const int sh = g_eid_shift;

    // ldmatrix per-lane address pieces (A tile, 528B row stride)
    const int ldsm_row = (lid & 7) + ((lid >> 3) & 1) * 8;   // row within 16
    const int ldsm_k16 = (lid >> 4) * 16;                    // +16B for k 8..15
    const uint32_t a_base = smem_base;

    // per-warp B fragment pointer (this warp's wn half), L1-resident
    const uint2* __restrict__ bfrag_w = g_bfrag + (size_t)(wn * 8) * 32 + lid;
    // epilogue column base for this thread: n = wn*64 + nb*8 + (lid&3)*2
    const int ncol0 = wn * 64 + (lid & 3) * 2;

    const float4 z4 = make_float4(0.f, 0.f, 0.f, 0.f);

    for (int t = blockIdx.x; t < num_tiles; t += gridDim.x) {
        const int m0 = t * TILE_M;

        // ========= producer: 4 pairs of edges, 2 chains interleaved =========
#pragma unroll 1
        for (int u = 0; u < 4; u++) {
            const int r0 = wid * 8 + 2 * u;          // tile row of edge 0
            const int e0 = m0 + r0;                  // edge 0 ; edge 1 = e0+1
            const bool g0 = (e0 < E), g1 = (e0 + 1 < E);

            // dst loads (2 independent, issued first)
            float4 dv0 = z4, dv1 = z4;
            if (g0) dv0 = __ldg(reinterpret_cast<const float4*>(
                dst_feat + (size_t)e0 * 128 + 4 * lid));
            if (g1) dv1 = __ldg(reinterpret_cast<const float4*>(
                dst_feat + (size_t)(e0 + 1) * 128 + 4 * lid));

            // segment metadata (branchless low-word dme reads)
            int me0 = 0, me1 = 0; float dg0 = 0.f, dg1 = 0.f;
            if (g0) { me0 = dst_max_eid[(size_t)e0 << sh];       dg0 = dst_deg[e0]; }
            if (g1) { me1 = dst_max_eid[(size_t)(e0 + 1) << sh]; dg1 = dst_deg[e0 + 1]; }
            if (me0 >= E) me0 = E - 1;  if (me0 < 0) me0 = 0;
            if (me1 >= E) me1 = E - 1;  if (me1 < 0) me1 = 0;
            int ss0 = me0 - (int)dg0 + 1;  if (ss0 < 0) ss0 = 0;
            int ss1 = me1 - (int)dg1 + 1;  if (ss1 < 0) ss1 = 0;
            int c0 = g0 ? (me0 - ss0 + 1) : 0;  if (c0 < 0) c0 = 0;
            int c1 = g1 ? (me1 - ss1 + 1) : 0;  if (c1 < 0) c1 = 0;

            const float4* p0 = reinterpret_cast<const float4*>(
                src_feat + (size_t)ss0 * 128 + 4 * lid);
            const float4* p1 = reinterpret_cast<const float4*>(
                src_feat + (size_t)ss1 * 128 + 4 * lid);

            // interleaved dual-chain segsum: 4 independent loads per iter
            float a0x = 0.f, a0y = 0.f, a0z = 0.f, a0w = 0.f;
            float a1x = 0.f, a1y = 0.f, a1z = 0.f, a1w = 0.f;
            int i0 = 0, i1 = 0;
#pragma unroll 1
            while ((i0 < c0) | (i1 < c1)) {
                float4 x0 = (i0     < c0) ? __ldg(p0 + (size_t)(i0)     * 32) : z4;
                float4 x1 = (i1     < c1) ? __ldg(p1 + (size_t)(i1)     * 32) : z4;
                float4 x2 = (i0 + 1 < c0) ? __ldg(p0 + (size_t)(i0 + 1) * 32) : z4;
                float4 x3 = (i1 + 1 < c1) ? __ldg(p1 + (size_t)(i1 + 1) * 32) : z4;
                a0x += x0.x + x2.x; a0y += x0.y + x2.y;
                a0z += x0.z + x2.z; a0w += x0.w + x2.w;
                a1x += x1.x + x3.x; a1y += x1.y + x3.y;
                a1z += x1.z + x3.z; a1w += x1.w + x3.w;
                i0 += 2; i1 += 2;
            }

            // stores: dst halves + hn halves (fp16)
            if (g0) {
                const float inv0 = 1.0f / (dg0 + 1.0f);
                uint32_t addr = a_base + (uint32_t)r0 * A_STRIDE_B + 8u * lid;
                uint32_t d01 = f22u(dv0.x, dv0.y), d23 = f22u(dv0.z, dv0.w);
                asm volatile("st.shared.v2.b32 [%0], {%1,%2};"
                             :: "r"(addr), "r"(d01), "r"(d23) : "memory");
                uint32_t h01 = f22u(a0x * inv0, a0y * inv0);
                uint32_t h23 = f22u(a0z * inv0, a0w * inv0);
                asm volatile("st.shared.v2.b32 [%0], {%1,%2};"
                             :: "r"(addr + 256u), "r"(h01), "r"(h23) : "memory");
            }
            if (g1) {
                const float inv1 = 1.0f / (dg1 + 1.0f);
                uint32_t addr = a_base + (uint32_t)(r0 + 1) * A_STRIDE_B + 8u * lid;
                uint32_t d01 = f22u(dv1.x, dv1.y), d23 = f22u(dv1.z, dv1.w);
                asm volatile("st.shared.v2.b32 [%0], {%1,%2};"
                             :: "r"(addr), "r"(d01), "r"(d23) : "memory");
                uint32_t h01 = f22u(a1x * inv1, a1y * inv1);
                uint32_t h23 = f22u(a1z * inv1, a1w * inv1);
                asm volatile("st.shared.v2.b32 [%0], {%1,%2};"
                             :: "r"(addr + 256u), "r"(h01), "r"(h23) : "memory");
            }
        }
        __syncthreads();

        // ========= MMA phase: warp tile 16x64, K=256 ========================
        float acc[8][4];
#pragma unroll
        for (int nb = 0; nb < 8; nb++)
#pragma unroll
            for (int q = 0; q < 4; q++) acc[nb][q] = 0.f;

        {
            const uint2* bp = bfrag_w;               // walks +16*32 per s
            uint32_t a_addr = a_base + (uint32_t)(wm * 16 + ldsm_row) * A_STRIDE_B
                            + (uint32_t)ldsm_k16;
#pragma unroll 4
            for (int s = 0; s < 16; s++) {
                uint32_t a[4];
                asm volatile(
                    "ldmatrix.sync.aligned.m8n8.x4.shared.b16 {%0,%1,%2,%3}, [%4];"
                    : "=r"(a[0]), "=r"(a[1]), "=r"(a[2]), "=r"(a[3])
                    : "r"(a_addr));
                a_addr += 32u;
#pragma unroll
                for (int nb = 0; nb < 8; nb++) {
                    uint2 b = __ldg(bp + (size_t)nb * 32);
                    mma16816(acc[nb], a, b.x, b.y);
                }
                bp += 16 * 32;
            }
        }
        __syncthreads();   // A reads complete; next-tile producer may overwrite

        // ========= epilogue: direct fragment stores with bias ===============
        // fragment rows: e0 = m0 + wm*16 + (lid>>2), e1 = e0 + 8
        // fragment cols: n = wn*64 + nb*8 + (lid&3)*2  (pair n, n+1)
        {
            const int er0 = m0 + wm * 16 + (lid >> 2);
            const int er1 = er0 + 8;
            const bool ge0 = (er0 < E), ge1 = (er1 < E);
            float* o0 = out + (size_t)er0 * 128 + ncol0;
            float* o1 = out + (size_t)er1 * 128 + ncol0;
#pragma unroll
            for (int nb = 0; nb < 8; nb++) {
                float2 bv = __ldg(g_bias2 + ((ncol0 + nb * 8) >> 1));
                if (ge0) {
                    float2 v0 = make_float2(acc[nb][0] + bv.x, acc[nb][1] + bv.y);
                    *reinterpret_cast<float2*>(o0 + nb * 8) = v0;
                }
                if (ge1) {
                    float2 v1 = make_float2(acc[nb][2] + bv.x, acc[nb][3] + bv.y);
                    *reinterpret_cast<float2*>(o1 + nb * 8) = v1;
                }
            }
        }
        // no barrier needed here: next loop iteration's producer writes A only
        // after the sync above; stores are fire-and-forget.
    }
}

// ============================================================================
// Launch
// ============================================================================
extern "C" void kernel_launch(void* const* d_in, const int* in_sizes, int n_in,
                              void* d_out, int out_size) {
    const float* src   = (const float*)d_in[0];   // src_feat   [E,128] f32
    const float* dstf  = (const float*)d_in[1];   // dst_feat   [E,128] f32
    // d_in[2] = dst_ids (unused: seg_start = dst_max_eid - deg + 1)
    const int*   dme   = (const int*)  d_in[3];   // dst_max_eid [E] i32 or i64
    const float* deg   = (const float*)d_in[4];   // dst_deg    [E] f32
    const float* Wself = (const float*)d_in[5];   // [128,128] f32
    const float* bself = (const float*)d_in[6];   // [128] f32
    const float* Wnei  = (const float*)d_in[7];   // [128,128] f32
    const float* bnei  = (const float*)d_in[8];   // [128] f32
    float* out = (float*)d_out;

    const int E = in_sizes[4];
    const int num_tiles = (E + TILE_M - 1) / TILE_M;

    prep_w_kernel<<<32, 256>>>(Wself, Wnei, bself, bnei, (const unsigned*)dme, E);

    int sm_count = 148;
    cudaDeviceGetAttribute(&sm_count, cudaDevAttrMultiProcessorCount, 0);
    int grid = OCC * sm_count;
    if (grid > num_tiles) grid = num_tiles;

    cudaFuncSetAttribute(fused_tsage_kernel,
                         cudaFuncAttributeMaxDynamicSharedMemorySize, SMEM_TOTAL);
    fused_tsage_kernel<<<grid, NTHREADS, SMEM_TOTAL>>>(
        src, dstf, dme, deg, out, E, num_tiles);
}

// round 16
// speedup vs baseline: 1.0921x; 1.0010x over previous
#include <cuda_runtime.h>
#include <cuda_fp16.h>
#include <cstdint>

// ============================================================================
// FastTSAGEConv fused kernel for GB300 (plain sm_103 PTX feature set):
// legacy HMMA mma.sync.m16n8k16 fp16 (fp32 accum), 1-pass.
//
//   ss = seg_start (dst_deg = dst_max_eid - seg_start + 1)
//   hn[e]  = (sum_{j=ss..me} src_feat[j]) / (deg[e]+1)
//   out[e] = [dst_feat[e] | hn[e]] @ [W_self; W_neigh] + (b_self + b_neigh)
//
// R15 -> R16: double-buffered A tile + ONE barrier per tile. R15's direct
// epilogue shrank smem to the A tile alone, enabling 2 buffers at OCC 3
// (2*33.8KB*3 = 203KB <= 228KB). A warp now starts producing tile t+1 the
// moment its own MMA of tile t finishes -- its segsum latency overlaps other
// warps' MMA instead of a barrier wait (straggler decoupling, the thing this
// workload punishes hardest). Safety: reads of buf p (MMA k) all precede
// sync(k+1); next writes to buf p (produce k+2) follow sync(k+1).
// ============================================================================

#define TILE_M     64
#define NTHREADS   256
#define OCC        3

// ---- smem layout: two A tiles ----
static constexpr int A_STRIDE_B = 528;          // bytes per A row (256 fp16 + 8 pad)
static constexpr int A_TILE_B   = TILE_M * A_STRIDE_B;     // 33792
static constexpr int SMEM_TOTAL = 2 * A_TILE_B;            // 67584

// Pre-packed B fragments: [kstep 0..15][nblock 0..15][lane 0..31] x 2 u32
// (64 KB, stays hot in L1 across the whole kernel)
__device__ uint2 g_bfrag[16 * 16 * 32];
// combined bias b_self + b_neigh, read as float2 (L1-resident)
__device__ float2 g_bias2[64];
// dtype shift for dst_max_eid: 1 if int64 (low word of e at index e<<1), 0 if int32
__device__ int g_eid_shift;

// ============================ helpers ===================================
__device__ __forceinline__ uint32_t smem_to_u32(const void* smem_ptr) {
    uint32_t addr;
    asm("{ .reg .u64 tmp; cvta.to.shared.u64 tmp, %1; cvt.u32.u64 %0, tmp; }"
        : "=r"(addr) : "l"(smem_ptr));
    return addr;
}

__device__ __forceinline__ uint32_t f22u(float a, float b) {
    __half2 h = __floats2half2_rn(a, b);
    return *reinterpret_cast<uint32_t*>(&h);
}

__device__ __forceinline__ void mma16816(float* c, const uint32_t* a,
                                         uint32_t b0, uint32_t b1) {
    asm volatile(
        "mma.sync.aligned.m16n8k16.row.col.f32.f16.f16.f32 "
        "{%0,%1,%2,%3}, {%4,%5,%6,%7}, {%8,%9}, {%0,%1,%2,%3};\n"
        : "+f"(c[0]), "+f"(c[1]), "+f"(c[2]), "+f"(c[3])
        : "r"(a[0]), "r"(a[1]), "r"(a[2]), "r"(a[3]), "r"(b0), "r"(b1));
}

// ============================================================================
// Prep kernel (dtype probe in block 0, bias pack in block 1): pack
// B = [W_self; W_neigh] (256 x 128 f32) into fp16 MMA fragment layout.
// For kstep s (k0=16s), nblock nb (n0=8nb), lane l:
//   kA = 16s + (l%4)*2,  n = 8nb + l/4
//   reg0 = half2( B[kA][n],   B[kA+1][n] )
//   reg1 = half2( B[kA+8][n], B[kA+9][n] )
// Probe: view dst_max_eid as int64 at elements [E/4, E/4+256) (word indices
// < E under either dtype). True int64 (values in [0,E)) => all high words 0;
// int32 data there holds values ~E/2 != 0.
// ============================================================================
__global__ void prep_w_kernel(const float* __restrict__ Wself,
                              const float* __restrict__ Wneigh,
                              const float* __restrict__ bself,
                              const float* __restrict__ bneigh,
                              const unsigned* __restrict__ dme_words, int E) {
    if (blockIdx.x == 0) {
        __shared__ int nz;
        if (threadIdx.x == 0) nz = 0;
        __syncthreads();
        int i = E / 4 + threadIdx.x;
        unsigned hi = dme_words[2 * i + 1];
        if (hi != 0u) atomicAdd(&nz, 1);
        __syncthreads();
        if (threadIdx.x == 0) g_eid_shift = (nz == 0) ? 1 : 0;
    }
    if (blockIdx.x == 1 && threadIdx.x < 64) {
        int n = threadIdx.x * 2;
        g_bias2[threadIdx.x] = make_float2(bself[n] + bneigh[n],
                                           bself[n + 1] + bneigh[n + 1]);
    }
    int idx = blockIdx.x * blockDim.x + threadIdx.x;    // 0..8191
    if (idx >= 16 * 16 * 32) return;
    int lane = idx & 31;
    int nb   = (idx >> 5) & 15;
    int s    = idx >> 9;
    int k0 = s * 16 + (lane & 3) * 2;
    int n  = nb * 8 + (lane >> 2);

    auto wc = [&](int k) -> float {
        return (k < 128) ? Wself[k * 128 + n] : Wneigh[(k - 128) * 128 + n];
    };
    uint2 v;
    v.x = f22u(wc(k0),     wc(k0 + 1));
    v.y = f22u(wc(k0 + 8), wc(k0 + 9));
    g_bfrag[idx] = v;
}

// ============================================================================
// Main persistent kernel — 3 CTAs/SM, double-buffered A, 1 barrier/tile
// ============================================================================
__global__ void __launch_bounds__(NTHREADS, OCC)
fused_tsage_kernel(const float* __restrict__ src_feat,
                   const float* __restrict__ dst_feat,
                   const int*   __restrict__ dst_max_eid,
                   const float* __restrict__ dst_deg,
                   float* __restrict__ out,
                   int E, int num_tiles) {
    extern __shared__ char smem[];
    const uint32_t smem_base = smem_to_u32(smem);
    const int tid = threadIdx.x;
    const int wid = tid >> 5;
    const int lid = tid & 31;
    const int wm  = wid & 3;        // M-warp 0..3  (rows wm*16 .. +15)
    const int wn  = wid >> 2;       // N-warp 0..1  (cols wn*64 .. +63)
    // branchless dme access: low word of element e = dst_max_eid[e << sh]
    const int sh = g_eid_shift;

    // ldmatrix per-lane address pieces (A tile, 528B row stride)
    const int ldsm_row = (lid & 7) + ((lid >> 3) & 1) * 8;   // row within 16
    const int ldsm_k16 = (lid >> 4) * 16;                    // +16B for k 8..15

    // per-warp B fragment pointer (this warp's wn half), L1-resident
    const uint2* __restrict__ bfrag_w = g_bfrag + (size_t)(wn * 8) * 32 + lid;
    // epilogue column base for this thread: n = wn*64 + nb*8 + (lid&3)*2
    const int ncol0 = wn * 64 + (lid & 3) * 2;

    const float4 z4 = make_float4(0.f, 0.f, 0.f, 0.f);

    // producer for one tile into the given A buffer
    auto produce = [&](int m0, uint32_t a_base) {
#pragma unroll 1
        for (int u = 0; u < 4; u++) {
            const int r0 = wid * 8 + 2 * u;          // tile row of edge 0
            const int e0 = m0 + r0;                  // edge 0 ; edge 1 = e0+1
            const bool g0 = (e0 < E), g1 = (e0 + 1 < E);

            float4 dv0 = z4, dv1 = z4;
            if (g0) dv0 = __ldg(reinterpret_cast<const float4*>(
                dst_feat + (size_t)e0 * 128 + 4 * lid));
            if (g1) dv1 = __ldg(reinterpret_cast<const float4*>(
                dst_feat + (size_t)(e0 + 1) * 128 + 4 * lid));

            int me0 = 0, me1 = 0; float dg0 = 0.f, dg1 = 0.f;
            if (g0) { me0 = dst_max_eid[(size_t)e0 << sh];       dg0 = dst_deg[e0]; }
            if (g1) { me1 = dst_max_eid[(size_t)(e0 + 1) << sh]; dg1 = dst_deg[e0 + 1]; }
            if (me0 >= E) me0 = E - 1;  if (me0 < 0) me0 = 0;
            if (me1 >= E) me1 = E - 1;  if (me1 < 0) me1 = 0;
            int ss0 = me0 - (int)dg0 + 1;  if (ss0 < 0) ss0 = 0;
            int ss1 = me1 - (int)dg1 + 1;  if (ss1 < 0) ss1 = 0;
            int c0 = g0 ? (me0 - ss0 + 1) : 0;  if (c0 < 0) c0 = 0;
            int c1 = g1 ? (me1 - ss1 + 1) : 0;  if (c1 < 0) c1 = 0;

            const float4* p0 = reinterpret_cast<const float4*>(
                src_feat + (size_t)ss0 * 128 + 4 * lid);
            const float4* p1 = reinterpret_cast<const float4*>(
                src_feat + (size_t)ss1 * 128 + 4 * lid);

            float a0x = 0.f, a0y = 0.f, a0z = 0.f, a0w = 0.f;
            float a1x = 0.f, a1y = 0.f, a1z = 0.f, a1w = 0.f;
            int i0 = 0, i1 = 0;
#pragma unroll 1
            while ((i0 < c0) | (i1 < c1)) {
                float4 x0 = (i0     < c0) ? __ldg(p0 + (size_t)(i0)     * 32) : z4;
                float4 x1 = (i1     < c1) ? __ldg(p1 + (size_t)(i1)     * 32) : z4;
                float4 x2 = (i0 + 1 < c0) ? __ldg(p0 + (size_t)(i0 + 1) * 32) : z4;
                float4 x3 = (i1 + 1 < c1) ? __ldg(p1 + (size_t)(i1 + 1) * 32) : z4;
                a0x += x0.x + x2.x; a0y += x0.y + x2.y;
                a0z += x0.z + x2.z; a0w += x0.w + x2.w;
                a1x += x1.x + x3.x; a1y += x1.y + x3.y;
                a1z += x1.z + x3.z; a1w += x1.w + x3.w;
                i0 += 2; i1 += 2;
            }

            if (g0) {
                const float inv0 = 1.0f / (dg0 + 1.0f);
                uint32_t addr = a_base + (uint32_t)r0 * A_STRIDE_B + 8u * lid;
                uint32_t d01 = f22u(dv0.x, dv0.y), d23 = f22u(dv0.z, dv0.w);
                asm volatile("st.shared.v2.b32 [%0], {%1,%2};"
                             :: "r"(addr), "r"(d01), "r"(d23) : "memory");
                uint32_t h01 = f22u(a0x * inv0, a0y * inv0);
                uint32_t h23 = f22u(a0z * inv0, a0w * inv0);
                asm volatile("st.shared.v2.b32 [%0], {%1,%2};"
                             :: "r"(addr + 256u), "r"(h01), "r"(h23) : "memory");
            }
            if (g1) {
                const float inv1 = 1.0f / (dg1 + 1.0f);
                uint32_t addr = a_base + (uint32_t)(r0 + 1) * A_STRIDE_B + 8u * lid;
                uint32_t d01 = f22u(dv1.x, dv1.y), d23 = f22u(dv1.z, dv1.w);
                asm volatile("st.shared.v2.b32 [%0], {%1,%2};"
                             :: "r"(addr), "r"(d01), "r"(d23) : "memory");
                uint32_t h01 = f22u(a1x * inv1, a1y * inv1);
                uint32_t h23 = f22u(a1z * inv1, a1w * inv1);
                asm volatile("st.shared.v2.b32 [%0], {%1,%2};"
                             :: "r"(addr + 256u), "r"(h01), "r"(h23) : "memory");
            }
        }
    };

    // ---- software pipeline: produce(t0) ; [sync; MMA(t); produce(t+1)]* ----
    int t = blockIdx.x;
    int p = 0;                                    // buffer parity
    if (t < num_tiles) produce(t * TILE_M, smem_base + p * A_TILE_B);

    for (; t < num_tiles; t += gridDim.x) {
        const int m0 = t * TILE_M;
        const uint32_t a_base = smem_base + p * A_TILE_B;
        __syncthreads();                          // buf p fully produced

        // ========= MMA phase: warp tile 16x64, K=256 ========================
        float acc[8][4];
#pragma unroll
        for (int nb = 0; nb < 8; nb++)
#pragma unroll
            for (int q = 0; q < 4; q++) acc[nb][q] = 0.f;

        {
            const uint2* bp = bfrag_w;               // walks +16*32 per s
            uint32_t a_addr = a_base + (uint32_t)(wm * 16 + ldsm_row) * A_STRIDE_B
                            + (uint32_t)ldsm_k16;
#pragma unroll 4
            for (int s = 0; s < 16; s++) {
                uint32_t a[4];
                asm volatile(
                    "ldmatrix.sync.aligned.m8n8.x4.shared.b16 {%0,%1,%2,%3}, [%4];"
                    : "=r"(a[0]), "=r"(a[1]), "=r"(a[2]), "=r"(a[3])
                    : "r"(a_addr));
                a_addr += 32u;
#pragma unroll
                for (int nb = 0; nb < 8; nb++) {
                    uint2 b = __ldg(bp + (size_t)nb * 32);
                    mma16816(acc[nb], a, b.x, b.y);
                }
                bp += 16 * 32;
            }
        }

        // ========= epilogue: direct fragment stores with bias ===============
        {
            const int er0 = m0 + wm * 16 + (lid >> 2);
            const int er1 = er0 + 8;
            const bool ge0 = (er0 < E), ge1 = (er1 < E);
            float* o0 = out + (size_t)er0 * 128 + ncol0;
            float* o1 = out + (size_t)er1 * 128 + ncol0;
#pragma unroll
            for (int nb = 0; nb < 8; nb++) {
                float2 bv = __ldg(g_bias2 + ((ncol0 + nb * 8) >> 1));
                if (ge0) {
                    float2 v0 = make_float2(acc[nb][0] + bv.x, acc[nb][1] + bv.y);
                    *reinterpret_cast<float2*>(o0 + nb * 8) = v0;
                }
                if (ge1) {
                    float2 v1 = make_float2(acc[nb][2] + bv.x, acc[nb][3] + bv.y);
                    *reinterpret_cast<float2*>(o1 + nb * 8) = v1;
                }
            }
        }

        // ========= produce next tile into the OTHER buffer (no barrier) =====
        const int tn = t + gridDim.x;
        p ^= 1;
        if (tn < num_tiles) produce(tn * TILE_M, smem_base + p * A_TILE_B);
    }
}

// ============================================================================
// Launch
// ============================================================================
extern "C" void kernel_launch(void* const* d_in, const int* in_sizes, int n_in,
                              void* d_out, int out_size) {
    const float* src   = (const float*)d_in[0];   // src_feat   [E,128] f32
    const float* dstf  = (const float*)d_in[1];   // dst_feat   [E,128] f32
    // d_in[2] = dst_ids (unused: seg_start = dst_max_eid - deg + 1)
    const int*   dme   = (const int*)  d_in[3];   // dst_max_eid [E] i32 or i64
    const float* deg   = (const float*)d_in[4];   // dst_deg    [E] f32
    const float* Wself = (const float*)d_in[5];   // [128,128] f32
    const float* bself = (const float*)d_in[6];   // [128] f32
    const float* Wnei  = (const float*)d_in[7];   // [128,128] f32
    const float* bnei  = (const float*)d_in[8];   // [128] f32
    float* out = (float*)d_out;

    const int E = in_sizes[4];
    const int num_tiles = (E + TILE_M - 1) / TILE_M;

    prep_w_kernel<<<32, 256>>>(Wself, Wnei, bself, bnei, (const unsigned*)dme, E);

    int sm_count = 148;
    cudaDeviceGetAttribute(&sm_count, cudaDevAttrMultiProcessorCount, 0);
    int grid = OCC * sm_count;
    if (grid > num_tiles) grid = num_tiles;

    cudaFuncSetAttribute(fused_tsage_kernel,
                         cudaFuncAttributeMaxDynamicSharedMemorySize, SMEM_TOTAL);
    fused_tsage_kernel<<<grid, NTHREADS, SMEM_TOTAL>>>(
        src, dstf, dme, deg, out, E, num_tiles);
}

// round 17
// speedup vs baseline: 1.1277x; 1.0326x over previous
#include <cuda_runtime.h>
#include <cuda_fp16.h>
#include <cstdint>

// ============================================================================
// FastTSAGEConv fused kernel for GB300 (plain sm_103 PTX feature set):
// legacy HMMA mma.sync.m16n8k16 fp16 (fp32 accum), 1-pass.
//
//   ss = seg_start (dst_deg = dst_max_eid - seg_start + 1)
//   hn[e]  = (sum_{j=ss..me} src_feat[j]) / (deg[e]+1)
//   out[e] = [dst_feat[e] | hn[e]] @ [W_self; W_neigh] + (b_self + b_neigh)
//
// R16 -> R17: all variants plateau at ~266 with L1=55% dominant; wavefront
// accounting shows B-fragment LDGs (128/warp/tile at warp tile M=16) are the
// largest L1 consumer. Re-shape warp grid 4Mx2N -> 2Mx4N (warp tile 32x32):
// B loads halve (64/warp/tile), ldmatrix doubles (cheap), acc regs unchanged
// (2 frag x 4 nb x 4 = 32). Frame otherwise = R16 (OCC 3, double-buffered A,
// 1 barrier/tile, direct epilogue, dual-chain producer).
// ============================================================================

#define TILE_M     64
#define NTHREADS   256
#define OCC        3

// ---- smem layout: two A tiles ----
static constexpr int A_STRIDE_B = 528;          // bytes per A row (256 fp16 + 8 pad)
static constexpr int A_TILE_B   = TILE_M * A_STRIDE_B;     // 33792
static constexpr int SMEM_TOTAL = 2 * A_TILE_B;            // 67584

// Pre-packed B fragments: [kstep 0..15][nblock 0..15][lane 0..31] x 2 u32
// (64 KB, stays hot in L1 across the whole kernel)
__device__ uint2 g_bfrag[16 * 16 * 32];
// combined bias b_self + b_neigh, read as float2 (L1-resident)
__device__ float2 g_bias2[64];
// dtype shift for dst_max_eid: 1 if int64 (low word of e at index e<<1), 0 if int32
__device__ int g_eid_shift;

// ============================ helpers ===================================
__device__ __forceinline__ uint32_t smem_to_u32(const void* smem_ptr) {
    uint32_t addr;
    asm("{ .reg .u64 tmp; cvta.to.shared.u64 tmp, %1; cvt.u32.u64 %0, tmp; }"
        : "=r"(addr) : "l"(smem_ptr));
    return addr;
}

__device__ __forceinline__ uint32_t f22u(float a, float b) {
    __half2 h = __floats2half2_rn(a, b);
    return *reinterpret_cast<uint32_t*>(&h);
}

__device__ __forceinline__ void mma16816(float* c, const uint32_t* a,
                                         uint32_t b0, uint32_t b1) {
    asm volatile(
        "mma.sync.aligned.m16n8k16.row.col.f32.f16.f16.f32 "
        "{%0,%1,%2,%3}, {%4,%5,%6,%7}, {%8,%9}, {%0,%1,%2,%3};\n"
        : "+f"(c[0]), "+f"(c[1]), "+f"(c[2]), "+f"(c[3])
        : "r"(a[0]), "r"(a[1]), "r"(a[2]), "r"(a[3]), "r"(b0), "r"(b1));
}

// ============================================================================
// Prep kernel (dtype probe in block 0, bias pack in block 1): pack
// B = [W_self; W_neigh] (256 x 128 f32) into fp16 MMA fragment layout.
// For kstep s (k0=16s), nblock nb (n0=8nb), lane l:
//   kA = 16s + (l%4)*2,  n = 8nb + l/4
//   reg0 = half2( B[kA][n],   B[kA+1][n] )
//   reg1 = half2( B[kA+8][n], B[kA+9][n] )
// Probe: view dst_max_eid as int64 at elements [E/4, E/4+256) (word indices
// < E under either dtype). True int64 (values in [0,E)) => all high words 0;
// int32 data there holds values ~E/2 != 0.
// ============================================================================
__global__ void prep_w_kernel(const float* __restrict__ Wself,
                              const float* __restrict__ Wneigh,
                              const float* __restrict__ bself,
                              const float* __restrict__ bneigh,
                              const unsigned* __restrict__ dme_words, int E) {
    if (blockIdx.x == 0) {
        __shared__ int nz;
        if (threadIdx.x == 0) nz = 0;
        __syncthreads();
        int i = E / 4 + threadIdx.x;
        unsigned hi = dme_words[2 * i + 1];
        if (hi != 0u) atomicAdd(&nz, 1);
        __syncthreads();
        if (threadIdx.x == 0) g_eid_shift = (nz == 0) ? 1 : 0;
    }
    if (blockIdx.x == 1 && threadIdx.x < 64) {
        int n = threadIdx.x * 2;
        g_bias2[threadIdx.x] = make_float2(bself[n] + bneigh[n],
                                           bself[n + 1] + bneigh[n + 1]);
    }
    int idx = blockIdx.x * blockDim.x + threadIdx.x;    // 0..8191
    if (idx >= 16 * 16 * 32) return;
    int lane = idx & 31;
    int nb   = (idx >> 5) & 15;
    int s    = idx >> 9;
    int k0 = s * 16 + (lane & 3) * 2;
    int n  = nb * 8 + (lane >> 2);

    auto wc = [&](int k) -> float {
        return (k < 128) ? Wself[k * 128 + n] : Wneigh[(k - 128) * 128 + n];
    };
    uint2 v;
    v.x = f22u(wc(k0),     wc(k0 + 1));
    v.y = f22u(wc(k0 + 8), wc(k0 + 9));
    g_bfrag[idx] = v;
}

// ============================================================================
// Main persistent kernel — 3 CTAs/SM, double-buffered A, 1 barrier/tile,
// warp tile 32x32 (2 M-warps x 4 N-warps)
// ============================================================================
__global__ void __launch_bounds__(NTHREADS, OCC)
fused_tsage_kernel(const float* __restrict__ src_feat,
                   const float* __restrict__ dst_feat,
                   const int*   __restrict__ dst_max_eid,
                   const float* __restrict__ dst_deg,
                   float* __restrict__ out,
                   int E, int num_tiles) {
    extern __shared__ char smem[];
    const uint32_t smem_base = smem_to_u32(smem);
    const int tid = threadIdx.x;
    const int wid = tid >> 5;
    const int lid = tid & 31;
    const int wm  = wid & 1;        // M-warp 0..1  (rows wm*32 .. +31)
    const int wn  = wid >> 1;       // N-warp 0..3  (cols wn*32 .. +31)
    // branchless dme access: low word of element e = dst_max_eid[e << sh]
    const int sh = g_eid_shift;

    // ldmatrix per-lane address pieces (A tile, 528B row stride)
    const int ldsm_row = (lid & 7) + ((lid >> 3) & 1) * 8;   // row within 16
    const int ldsm_k16 = (lid >> 4) * 16;                    // +16B for k 8..15

    // per-warp B fragment pointer: this warp's 4 nblocks start at wn*4
    const uint2* __restrict__ bfrag_w = g_bfrag + (size_t)(wn * 4) * 32 + lid;
    // epilogue column base for this thread: n = wn*32 + nb*8 + (lid&3)*2
    const int ncol0 = wn * 32 + (lid & 3) * 2;

    const float4 z4 = make_float4(0.f, 0.f, 0.f, 0.f);

    // producer for one tile into the given A buffer (warp-per-8-edges)
    auto produce = [&](int m0, uint32_t a_base) {
#pragma unroll 1
        for (int u = 0; u < 4; u++) {
            const int r0 = wid * 8 + 2 * u;          // tile row of edge 0
            const int e0 = m0 + r0;                  // edge 0 ; edge 1 = e0+1
            const bool g0 = (e0 < E), g1 = (e0 + 1 < E);

            float4 dv0 = z4, dv1 = z4;
            if (g0) dv0 = __ldg(reinterpret_cast<const float4*>(
                dst_feat + (size_t)e0 * 128 + 4 * lid));
            if (g1) dv1 = __ldg(reinterpret_cast<const float4*>(
                dst_feat + (size_t)(e0 + 1) * 128 + 4 * lid));

            int me0 = 0, me1 = 0; float dg0 = 0.f, dg1 = 0.f;
            if (g0) { me0 = dst_max_eid[(size_t)e0 << sh];       dg0 = dst_deg[e0]; }
            if (g1) { me1 = dst_max_eid[(size_t)(e0 + 1) << sh]; dg1 = dst_deg[e0 + 1]; }
            if (me0 >= E) me0 = E - 1;  if (me0 < 0) me0 = 0;
            if (me1 >= E) me1 = E - 1;  if (me1 < 0) me1 = 0;
            int ss0 = me0 - (int)dg0 + 1;  if (ss0 < 0) ss0 = 0;
            int ss1 = me1 - (int)dg1 + 1;  if (ss1 < 0) ss1 = 0;
            int c0 = g0 ? (me0 - ss0 + 1) : 0;  if (c0 < 0) c0 = 0;
            int c1 = g1 ? (me1 - ss1 + 1) : 0;  if (c1 < 0) c1 = 0;

            const float4* p0 = reinterpret_cast<const float4*>(
                src_feat + (size_t)ss0 * 128 + 4 * lid);
            const float4* p1 = reinterpret_cast<const float4*>(
                src_feat + (size_t)ss1 * 128 + 4 * lid);

            float a0x = 0.f, a0y = 0.f, a0z = 0.f, a0w = 0.f;
            float a1x = 0.f, a1y = 0.f, a1z = 0.f, a1w = 0.f;
            int i0 = 0, i1 = 0;
#pragma unroll 1
            while ((i0 < c0) | (i1 < c1)) {
                float4 x0 = (i0     < c0) ? __ldg(p0 + (size_t)(i0)     * 32) : z4;
                float4 x1 = (i1     < c1) ? __ldg(p1 + (size_t)(i1)     * 32) : z4;
                float4 x2 = (i0 + 1 < c0) ? __ldg(p0 + (size_t)(i0 + 1) * 32) : z4;
                float4 x3 = (i1 + 1 < c1) ? __ldg(p1 + (size_t)(i1 + 1) * 32) : z4;
                a0x += x0.x + x2.x; a0y += x0.y + x2.y;
                a0z += x0.z + x2.z; a0w += x0.w + x2.w;
                a1x += x1.x + x3.x; a1y += x1.y + x3.y;
                a1z += x1.z + x3.z; a1w += x1.w + x3.w;
                i0 += 2; i1 += 2;
            }

            if (g0) {
                const float inv0 = 1.0f / (dg0 + 1.0f);
                uint32_t addr = a_base + (uint32_t)r0 * A_STRIDE_B + 8u * lid;
                uint32_t d01 = f22u(dv0.x, dv0.y), d23 = f22u(dv0.z, dv0.w);
                asm volatile("st.shared.v2.b32 [%0], {%1,%2};"
                             :: "r"(addr), "r"(d01), "r"(d23) : "memory");
                uint32_t h01 = f22u(a0x * inv0, a0y * inv0);
                uint32_t h23 = f22u(a0z * inv0, a0w * inv0);
                asm volatile("st.shared.v2.b32 [%0], {%1,%2};"
                             :: "r"(addr + 256u), "r"(h01), "r"(h23) : "memory");
            }
            if (g1) {
                const float inv1 = 1.0f / (dg1 + 1.0f);
                uint32_t addr = a_base + (uint32_t)(r0 + 1) * A_STRIDE_B + 8u * lid;
                uint32_t d01 = f22u(dv1.x, dv1.y), d23 = f22u(dv1.z, dv1.w);
                asm volatile("st.shared.v2.b32 [%0], {%1,%2};"
                             :: "r"(addr), "r"(d01), "r"(d23) : "memory");
                uint32_t h01 = f22u(a1x * inv1, a1y * inv1);
                uint32_t h23 = f22u(a1z * inv1, a1w * inv1);
                asm volatile("st.shared.v2.b32 [%0], {%1,%2};"
                             :: "r"(addr + 256u), "r"(h01), "r"(h23) : "memory");
            }
        }
    };

    // ---- software pipeline: produce(t0) ; [sync; MMA(t); produce(t+1)]* ----
    int t = blockIdx.x;
    int p = 0;                                    // buffer parity
    if (t < num_tiles) produce(t * TILE_M, smem_base + p * A_TILE_B);

    for (; t < num_tiles; t += gridDim.x) {
        const int m0 = t * TILE_M;
        const uint32_t a_base = smem_base + p * A_TILE_B;
        __syncthreads();                          // buf p fully produced

        // ========= MMA phase: warp tile 32x32, K=256 ========================
        float acc[2][4][4];
#pragma unroll
        for (int mi = 0; mi < 2; mi++)
#pragma unroll
            for (int nb = 0; nb < 4; nb++)
#pragma unroll
                for (int q = 0; q < 4; q++) acc[mi][nb][q] = 0.f;

        {
            const uint2* bp = bfrag_w;               // walks +16*32 per s
            uint32_t a_addr0 = a_base
                + (uint32_t)(wm * 32 + ldsm_row) * A_STRIDE_B + (uint32_t)ldsm_k16;
#pragma unroll 4
            for (int s = 0; s < 16; s++) {
                uint32_t a0[4], a1[4];
                asm volatile(
                    "ldmatrix.sync.aligned.m8n8.x4.shared.b16 {%0,%1,%2,%3}, [%4];"
                    : "=r"(a0[0]), "=r"(a0[1]), "=r"(a0[2]), "=r"(a0[3])
                    : "r"(a_addr0));
                asm volatile(
                    "ldmatrix.sync.aligned.m8n8.x4.shared.b16 {%0,%1,%2,%3}, [%4];"
                    : "=r"(a1[0]), "=r"(a1[1]), "=r"(a1[2]), "=r"(a1[3])
                    : "r"(a_addr0 + 16u * A_STRIDE_B));
                a_addr0 += 32u;
#pragma unroll
                for (int nb = 0; nb < 4; nb++) {
                    uint2 b = __ldg(bp + (size_t)nb * 32);
                    mma16816(acc[0][nb], a0, b.x, b.y);
                    mma16816(acc[1][nb], a1, b.x, b.y);
                }
                bp += 16 * 32;
            }
        }

        // ========= epilogue: direct fragment stores with bias ===============
        {
#pragma unroll
            for (int mi = 0; mi < 2; mi++) {
                const int er0 = m0 + wm * 32 + mi * 16 + (lid >> 2);
                const int er1 = er0 + 8;
                const bool ge0 = (er0 < E), ge1 = (er1 < E);
                float* o0 = out + (size_t)er0 * 128 + ncol0;
                float* o1 = out + (size_t)er1 * 128 + ncol0;
#pragma unroll
                for (int nb = 0; nb < 4; nb++) {
                    float2 bv = __ldg(g_bias2 + ((ncol0 + nb * 8) >> 1));
                    if (ge0) {
                        float2 v0 = make_float2(acc[mi][nb][0] + bv.x,
                                                acc[mi][nb][1] + bv.y);
                        *reinterpret_cast<float2*>(o0 + nb * 8) = v0;
                    }
                    if (ge1) {
                        float2 v1 = make_float2(acc[mi][nb][2] + bv.x,
                                                acc[mi][nb][3] + bv.y);
                        *reinterpret_cast<float2*>(o1 + nb * 8) = v1;
                    }
                }
            }
        }

        // ========= produce next tile into the OTHER buffer (no barrier) =====
        const int tn = t + gridDim.x;
        p ^= 1;
        if (tn < num_tiles) produce(tn * TILE_M, smem_base + p * A_TILE_B);
    }
}

// ============================================================================
// Launch
// ============================================================================
extern "C" void kernel_launch(void* const* d_in, const int* in_sizes, int n_in,
                              void* d_out, int out_size) {
    const float* src   = (const float*)d_in[0];   // src_feat   [E,128] f32
    const float* dstf  = (const float*)d_in[1];   // dst_feat   [E,128] f32
    // d_in[2] = dst_ids (unused: seg_start = dst_max_eid - deg + 1)
    const int*   dme   = (const int*)  d_in[3];   // dst_max_eid [E] i32 or i64
    const float* deg   = (const float*)d_in[4];   // dst_deg    [E] f32
    const float* Wself = (const float*)d_in[5];   // [128,128] f32
    const float* bself = (const float*)d_in[6];   // [128] f32
    const float* Wnei  = (const float*)d_in[7];   // [128,128] f32
    const float* bnei  = (const float*)d_in[8];   // [128] f32
    float* out = (float*)d_out;

    const int E = in_sizes[4];
    const int num_tiles = (E + TILE_M - 1) / TILE_M;

    prep_w_kernel<<<32, 256>>>(Wself, Wnei, bself, bnei, (const unsigned*)dme, E);

    int sm_count = 148;
    cudaDeviceGetAttribute(&sm_count, cudaDevAttrMultiProcessorCount, 0);
    int grid = OCC * sm_count;
    if (grid > num_tiles) grid = num_tiles;

    cudaFuncSetAttribute(fused_tsage_kernel,
                         cudaFuncAttributeMaxDynamicSharedMemorySize, SMEM_TOTAL);
    fused_tsage_kernel<<<grid, NTHREADS, SMEM_TOTAL>>>(
        src, dstf, dme, deg, out, E, num_tiles);
}